// round 7
// baseline (speedup 1.0000x reference)
#include <cuda_runtime.h>
#include <cuda_fp16.h>

// SemiConv2d (tropical conv): out[n,oc,h,w] = max_{ic,kh,kw} min(xpad, K)
// x: (8,32,96,96) f32, K: (32,32,3,3) f32, out f32, pad=1 with -inf.
//
// Sorted-tap exact early exit (descending k) + THREE column-shifted x copies
// in smem so every tap is a single aligned LDS.128. Taps processed in chunks
// of 4 with one exit check per chunk (against the chunk's largest k -> exact).

#define N_      8
#define IC_     32
#define OC_     32
#define H_      96
#define W_      96
#define TILE_H  8
#define XROWS   10           // TILE_H + 2 halo rows
#define XS_STRIDE 104        // halves per row (208 B, 16B multiple)
#define COPY_HALVES (IC_ * XROWS * XS_STRIDE)   // 33280
#define OC_PER_BLK 8
#define THREADS 768
#define NTAPS   288          // 32 ic * 9

__device__ unsigned g_taps[OC_ * NTAPS];  // per oc desc: (half_bits<<16)|(off_halves>>3)

// ---- prep: rank-sort taps per oc by fp16 value (desc), ties by index ----
__global__ void semiconv2d_prep(const float* __restrict__ kern) {
    __shared__ __half kv[NTAPS];
    const int oc = blockIdx.x;
    const int t  = threadIdx.x;
    __half me = __float2half_rn(kern[oc * NTAPS + t]);
    kv[t] = me;
    __syncthreads();
    int rank = 0;
    #pragma unroll 4
    for (int j = 0; j < NTAPS; j++) {
        __half kj = kv[j];
        rank += (__hgt(kj, me) || (__heq(kj, me) && j < t)) ? 1 : 0;
    }
    int ic = t / 9, r = t % 9, kh = r / 3, kw = r % 3;
    unsigned off = (unsigned)(kw * COPY_HALVES + (ic * XROWS + kh) * XS_STRIDE);
    g_taps[oc * NTAPS + rank] = ((unsigned)__half_as_ushort(me) << 16) | (off >> 3);
}

__global__ __launch_bounds__(THREADS, 1)
void semiconv2d_sorted3(const float* __restrict__ x,
                        float* __restrict__ out) {
    extern __shared__ __align__(16) char smraw[];
    __half*   xs    = (__half*)smraw;                          // 3 copies, shifted by 0/1/2 cols
    unsigned* tapss = (unsigned*)(smraw + (size_t)3 * COPY_HALVES * sizeof(__half));

    const int tid    = threadIdx.x;
    const int n      = blockIdx.z;
    const int ocbase = blockIdx.y * OC_PER_BLK;
    const int h0     = blockIdx.x * TILE_H;
    const __half  NEGH = __ushort_as_half((unsigned short)0xFC00);   // -inf
    const __half2 NEG2 = __half2half2(NEGH);

    // ---- fill x copies: copy c at col p holds xpad[p + c]; reads use cols <= 95 ----
    const float* xn = x + (size_t)n * IC_ * H_ * W_;
    for (int e = tid; e < COPY_HALVES; e += THREADS) {
        int rem = e % (XROWS * XS_STRIDE);
        int r   = rem / XS_STRIDE;
        int p   = rem % XS_STRIDE;
        int g   = h0 - 1 + r;
        __half v = NEGH;
        if (p >= 1 && p <= W_ && g >= 0 && g < H_) {
            int ic = e / (XROWS * XS_STRIDE);
            v = __float2half_rn(xn[(ic * H_ + g) * W_ + (p - 1)]);
        }
        xs[e] = v;                                     // copy 0
        if (p >= 1) xs[e - 1 + COPY_HALVES]     = v;   // copy 1
        if (p >= 2) xs[e - 2 + 2 * COPY_HALVES] = v;   // copy 2
    }
    // ---- sorted tap lists for this block's 8 ocs ----
    for (int e = tid; e < OC_PER_BLK * NTAPS; e += THREADS)
        tapss[e] = g_taps[ocbase * NTAPS + e];
    __syncthreads();

    // thread -> (local oc, h row, 8-wide w strip); warp is oc-uniform (96 thr/oc)
    const int ocl = tid / 96;
    const int s   = tid % 96;
    const int hl  = s / 12;
    const int w0  = (s % 12) * 8;
    const int h   = h0 + hl;

    __half2 acc0 = NEG2, acc1 = NEG2, acc2 = NEG2, acc3 = NEG2;

    const __half*   xb = xs + hl * XS_STRIDE + w0;     // + (rec&0xffff)<<3, 16B aligned
    const unsigned* tp = tapss + ocl * NTAPS;

    #pragma unroll 1
    for (int i = 0; i < NTAPS; i += 4) {
        uint4 r4 = *(const uint4*)(tp + i);
        // exact early exit: all 8 accs >= largest remaining k?
        __half2 kc = __half2half2(__ushort_as_half((unsigned short)(r4.x >> 16)));
        __half2 m  = __hmin2(__hmin2(acc0, acc1), __hmin2(acc2, acc3));
        if (__hbge2(m, kc)) break;

        {   // tap 0
            float4 xv = *(const float4*)(xb + ((r4.x & 0xffffu) << 3));
            __half2 k2 = __half2half2(__ushort_as_half((unsigned short)(r4.x >> 16)));
            acc0 = __hmax2(acc0, __hmin2(*(__half2*)&xv.x, k2));
            acc1 = __hmax2(acc1, __hmin2(*(__half2*)&xv.y, k2));
            acc2 = __hmax2(acc2, __hmin2(*(__half2*)&xv.z, k2));
            acc3 = __hmax2(acc3, __hmin2(*(__half2*)&xv.w, k2));
        }
        {   // tap 1
            float4 xv = *(const float4*)(xb + ((r4.y & 0xffffu) << 3));
            __half2 k2 = __half2half2(__ushort_as_half((unsigned short)(r4.y >> 16)));
            acc0 = __hmax2(acc0, __hmin2(*(__half2*)&xv.x, k2));
            acc1 = __hmax2(acc1, __hmin2(*(__half2*)&xv.y, k2));
            acc2 = __hmax2(acc2, __hmin2(*(__half2*)&xv.z, k2));
            acc3 = __hmax2(acc3, __hmin2(*(__half2*)&xv.w, k2));
        }
        {   // tap 2
            float4 xv = *(const float4*)(xb + ((r4.z & 0xffffu) << 3));
            __half2 k2 = __half2half2(__ushort_as_half((unsigned short)(r4.z >> 16)));
            acc0 = __hmax2(acc0, __hmin2(*(__half2*)&xv.x, k2));
            acc1 = __hmax2(acc1, __hmin2(*(__half2*)&xv.y, k2));
            acc2 = __hmax2(acc2, __hmin2(*(__half2*)&xv.z, k2));
            acc3 = __hmax2(acc3, __hmin2(*(__half2*)&xv.w, k2));
        }
        {   // tap 3
            float4 xv = *(const float4*)(xb + ((r4.w & 0xffffu) << 3));
            __half2 k2 = __half2half2(__ushort_as_half((unsigned short)(r4.w >> 16)));
            acc0 = __hmax2(acc0, __hmin2(*(__half2*)&xv.x, k2));
            acc1 = __hmax2(acc1, __hmin2(*(__half2*)&xv.y, k2));
            acc2 = __hmax2(acc2, __hmin2(*(__half2*)&xv.z, k2));
            acc3 = __hmax2(acc3, __hmin2(*(__half2*)&xv.w, k2));
        }
    }

    // ---- write 8 w outputs as f32 ----
    int oc = ocbase + ocl;
    float4* o = (float4*)(out + (((size_t)n * OC_ + oc) * H_ + h) * W_ + w0);
    float2 f0 = __half22float2(acc0);
    float2 f1 = __half22float2(acc1);
    float2 f2 = __half22float2(acc2);
    float2 f3 = __half22float2(acc3);
    o[0] = make_float4(f0.x, f0.y, f1.x, f1.y);
    o[1] = make_float4(f2.x, f2.y, f3.x, f3.y);
}

extern "C" void kernel_launch(void* const* d_in, const int* in_sizes, int n_in,
                              void* d_out, int out_size) {
    const float* x = (const float*)d_in[0];
    const float* k = (const float*)d_in[1];
    float* out = (float*)d_out;

    semiconv2d_prep<<<OC_, NTAPS>>>(k);

    size_t smem = (size_t)3 * COPY_HALVES * sizeof(__half)
                + (size_t)OC_PER_BLK * NTAPS * sizeof(unsigned);   // 199680 + 9216 = 208896
    cudaFuncSetAttribute(semiconv2d_sorted3,
                         cudaFuncAttributeMaxDynamicSharedMemorySize, (int)smem);
    dim3 grid(H_ / TILE_H, OC_ / OC_PER_BLK, N_);                  // 12 x 4 x 8 = 384
    semiconv2d_sorted3<<<grid, THREADS, smem>>>(x, out);
}

// round 8
// speedup vs baseline: 1.2297x; 1.2297x over previous
#include <cuda_runtime.h>
#include <cuda_fp16.h>

// SemiConv2d (tropical conv): out[n,oc,h,w] = max_{ic,kh,kw} min(xpad, K)
// x: (8,32,96,96) f32, K: (32,32,3,3) f32, out f32, pad=1 with -inf.
//
// Sorted-tap exact early exit (descending k). Single x copy in smem; each
// tap is branchless: LDS.128+LDS.64 of halves [w0..w0+11], kw-shift via
// PRMT with selector 0x3210 + kw*0x2222, exit check per 4-tap chunk.

#define N_      8
#define IC_     32
#define OC_     32
#define H_      96
#define W_      96
#define TILE_H  8
#define XROWS   10           // TILE_H + 2 halo rows
#define XS_STRIDE 104        // halves per row (208 B); col0 & cols>=97 = -inf
#define OC_PER_BLK 8
#define THREADS 768
#define NTAPS   288          // 32 ic * 9

// rec: [31:16]=k half bits, [15:2]=row offset in 8-half units, [1:0]=kw
__device__ unsigned g_taps[OC_ * NTAPS];

__global__ void semiconv2d_prep(const float* __restrict__ kern) {
    __shared__ __half kv[NTAPS];
    const int oc = blockIdx.x;
    const int t  = threadIdx.x;
    __half me = __float2half_rn(kern[oc * NTAPS + t]);
    kv[t] = me;
    __syncthreads();
    int rank = 0;
    #pragma unroll 4
    for (int j = 0; j < NTAPS; j++) {
        __half kj = kv[j];
        rank += (__hgt(kj, me) || (__heq(kj, me) && j < t)) ? 1 : 0;
    }
    int ic = t / 9, r = t % 9, kh = r / 3, kw = r % 3;
    unsigned off8 = (unsigned)(((ic * XROWS + kh) * XS_STRIDE) >> 3);   // XS_STRIDE % 8 == 0
    g_taps[oc * NTAPS + rank] =
        ((unsigned)__half_as_ushort(me) << 16) | (off8 << 2) | (unsigned)kw;
}

__global__ __launch_bounds__(THREADS, 2)
void semiconv2d_prmt(const float* __restrict__ x,
                     float* __restrict__ out) {
    extern __shared__ __align__(16) char smraw[];
    __half*   xs    = (__half*)smraw;                                   // [IC][XROWS][XS_STRIDE]
    unsigned* tapss = (unsigned*)(smraw + (size_t)IC_ * XROWS * XS_STRIDE * sizeof(__half));

    const int tid    = threadIdx.x;
    const int n      = blockIdx.z;
    const int ocbase = blockIdx.y * OC_PER_BLK;
    const int h0     = blockIdx.x * TILE_H;
    const __half  NEGH = __ushort_as_half((unsigned short)0xFC00);      // -inf
    const __half2 NEG2 = __half2half2(NEGH);

    // ---- fill x tile (f32 gmem -> f16 smem, -inf halo) ----
    const float* xn = x + (size_t)n * IC_ * H_ * W_;
    for (int e = tid; e < IC_ * XROWS * XS_STRIDE; e += THREADS) {
        int ic  = e / (XROWS * XS_STRIDE);
        int rem = e % (XROWS * XS_STRIDE);
        int r   = rem / XS_STRIDE;
        int c   = rem % XS_STRIDE;
        int g   = h0 - 1 + r;
        __half v = NEGH;
        if (c >= 1 && c <= W_ && g >= 0 && g < H_)
            v = __float2half_rn(xn[(ic * H_ + g) * W_ + (c - 1)]);
        xs[e] = v;
    }
    for (int e = tid; e < OC_PER_BLK * NTAPS; e += THREADS)
        tapss[e] = g_taps[ocbase * NTAPS + e];
    __syncthreads();

    // thread -> (local oc, h row, 8-wide w strip); warp is oc-uniform
    const int ocl = tid / 96;
    const int s   = tid % 96;
    const int hl  = s / 12;
    const int w0  = (s % 12) * 8;
    const int h   = h0 + hl;

    __half2 acc0 = NEG2, acc1 = NEG2, acc2 = NEG2, acc3 = NEG2;

    const __half*   xb = xs + hl * XS_STRIDE + w0;    // + row_off (8-half units * 8)
    const unsigned* tp = tapss + ocl * NTAPS;

    #pragma unroll 1
    for (int i = 0; i < NTAPS; i += 4) {
        uint4 r4 = *(const uint4*)(tp + i);
        // exact early exit vs chunk's largest k
        unsigned kc2 = __byte_perm(r4.x, r4.x, 0x3232);
        __half2 m = __hmin2(__hmin2(acc0, acc1), __hmin2(acc2, acc3));
        if (__hbge2(m, *(__half2*)&kc2)) break;

        unsigned recs[4] = {r4.x, r4.y, r4.z, r4.w};
        #pragma unroll
        for (int j = 0; j < 4; j++) {
            unsigned rec = recs[j];
            const __half* row = xb + ((rec >> 2) & 0x3fffu) * 8;
            uint4 va = *(const uint4*)row;            // halves 0..7
            uint2 vb = *(const uint2*)(row + 8);      // halves 8..11
            unsigned sel = 0x3210u + (rec & 3u) * 0x2222u;
            unsigned x0 = __byte_perm(va.x, va.y, sel);
            unsigned x1 = __byte_perm(va.y, va.z, sel);
            unsigned x2 = __byte_perm(va.z, va.w, sel);
            unsigned x3 = __byte_perm(va.w, vb.x, sel);
            unsigned k2 = __byte_perm(rec, rec, 0x3232);
            __half2 kk = *(__half2*)&k2;
            acc0 = __hmax2(acc0, __hmin2(*(__half2*)&x0, kk));
            acc1 = __hmax2(acc1, __hmin2(*(__half2*)&x1, kk));
            acc2 = __hmax2(acc2, __hmin2(*(__half2*)&x2, kk));
            acc3 = __hmax2(acc3, __hmin2(*(__half2*)&x3, kk));
        }
    }

    // ---- write 8 w outputs as f32 ----
    int oc = ocbase + ocl;
    float4* o = (float4*)(out + (((size_t)n * OC_ + oc) * H_ + h) * W_ + w0);
    float2 f0 = __half22float2(acc0);
    float2 f1 = __half22float2(acc1);
    float2 f2 = __half22float2(acc2);
    float2 f3 = __half22float2(acc3);
    o[0] = make_float4(f0.x, f0.y, f1.x, f1.y);
    o[1] = make_float4(f2.x, f2.y, f3.x, f3.y);
}

extern "C" void kernel_launch(void* const* d_in, const int* in_sizes, int n_in,
                              void* d_out, int out_size) {
    const float* x = (const float*)d_in[0];
    const float* k = (const float*)d_in[1];
    float* out = (float*)d_out;

    semiconv2d_prep<<<OC_, NTAPS>>>(k);

    size_t smem = (size_t)IC_ * XROWS * XS_STRIDE * sizeof(__half)
                + (size_t)OC_PER_BLK * NTAPS * sizeof(unsigned);   // 66560 + 9216 = 75776 B
    cudaFuncSetAttribute(semiconv2d_prmt,
                         cudaFuncAttributeMaxDynamicSharedMemorySize, (int)smem);
    dim3 grid(H_ / TILE_H, OC_ / OC_PER_BLK, N_);                  // 12 x 4 x 8 = 384
    semiconv2d_prmt<<<grid, THREADS, smem>>>(x, out);
}